// round 7
// baseline (speedup 1.0000x reference)
#include <cuda_runtime.h>

// AffineTransformation: B=32, H=W=512, C=1, fp32.
// d_in[0] = theta [32,6] f32, d_in[1] = image [32,512,512,1] f32 -> out same shape.
//
// Persistent single-wave grid: 1776 CTAs (148 SMs x 12 CTA/SM), each loops over
// tiles with stride 1776. Tile index decodes batch as (idx & 31) so each CTA's
// ~9 tiles spread across batches/regions -> per-CTA cost averaging, no wave
// transitions. Inner tile code = R4 (best verified): thread owns 4 vertical px,
// interior path batches all 16 gathers (MLP=16), border path = exact reference.

#define BB 32
#define HH 512
#define WW 512

#define NTILES   16384          // 16 col-tiles x 32 row-tiles x 32 batches
#define NBLOCKS  1776           // 148 * 12

__global__ __launch_bounds__(128, 12)
void affine_sample_kernel(const float* __restrict__ theta,
                          const float* __restrict__ image,
                          float* __restrict__ out)
{
    const int lane = threadIdx.x;        // 0..31 -> col within tile
    const int wy   = threadIdx.y;        // 0..3  -> 4-row group within tile

    for (int idx = blockIdx.x; idx < NTILES; idx += NBLOCKS) {
        const int b  = idx & 31;          // batch (fast-varying -> cost interleave)
        const int t  = idx >> 5;          // 0..511
        const int tx = t & 15;            // 16 col tiles
        const int ty = t >> 4;            // 32 row tiles

        const float t0 = __ldg(theta + b * 6 + 0);
        const float t1 = __ldg(theta + b * 6 + 1);
        const float t2 = __ldg(theta + b * 6 + 2);
        const float t3 = __ldg(theta + b * 6 + 3);
        const float t4 = __ldg(theta + b * 6 + 4);
        const float t5 = __ldg(theta + b * 6 + 5);

        const int col  = tx * 32 + lane;          // 0..511
        const int row0 = ty * 16 + wy * 4;        // 4 rows per thread

        const float inv_w = 2.0f / (float)(WW - 1);
        const float inv_h = 2.0f / (float)(HH - 1);
        const float xn  = -1.0f + (float)col  * inv_w;
        const float yn0 = -1.0f + (float)row0 * inv_h;

        // Pixel-space coords at j=0; d(fx)/d(row)=t1, d(fy)/d(row)=t4.
        const float fx0 = 0.5f * (float)(WW - 1) * (t0 * xn + t1 * yn0 + t2) + 0.5f * (float)(WW - 1);
        const float fy0 = 0.5f * (float)(HH - 1) * (t3 * xn + t4 * yn0 + t5) + 0.5f * (float)(HH - 1);
        const float fx3 = fmaf(3.0f, t1, fx0);
        const float fy3 = fmaf(3.0f, t4, fy0);

        const float lox = fminf(fx0, fx3), hix = fmaxf(fx0, fx3);
        const float loy = fminf(fy0, fy3), hiy = fmaxf(fy0, fy3);

        const int obase = (b * HH + row0) * WW + col;   // fits in int32

        // (c) whole 4-row span has zero coverage -> store zeros, no gathers
        if (hix <= -1.0f || lox >= (float)WW || hiy <= -1.0f || loy >= (float)HH) {
            #pragma unroll
            for (int j = 0; j < 4; j++) out[obase + j * WW] = 0.0f;
            continue;
        }

        const float* __restrict__ img = image + b * (HH * WW);

        float r[4];

        if (lox >= 0.0f && hix < (float)(WW - 1) && loy >= 0.0f && hiy < (float)(HH - 1)) {
            // (a) fully interior: no clamps, trunc == floor, plain bilinear lerp.
            float ax[4], ay[4];
            int   base[4];
            #pragma unroll
            for (int j = 0; j < 4; j++) {
                const float fx = fmaf((float)j, t1, fx0);
                const float fy = fmaf((float)j, t4, fy0);
                const int ix = (int)fx;
                const int iy = (int)fy;
                ax[j] = fx - (float)ix;
                ay[j] = fy - (float)iy;
                base[j] = iy * WW + ix;
            }
            float va[4], vb[4], vc[4], vd[4];
            #pragma unroll
            for (int j = 0; j < 4; j++) {
                va[j] = __ldg(img + base[j]);
                vb[j] = __ldg(img + base[j] + 1);
                vc[j] = __ldg(img + base[j] + WW);
                vd[j] = __ldg(img + base[j] + WW + 1);
            }
            #pragma unroll
            for (int j = 0; j < 4; j++) {
                const float h0 = fmaf(ax[j], vb[j] - va[j], va[j]);
                const float h1 = fmaf(ax[j], vd[j] - vc[j], vc[j]);
                r[j] = __saturatef(fmaf(ay[j], h1 - h0, h0));
            }
        } else {
            // (b) border: full reference semantics (clip-then-delta, edge double-count)
            #pragma unroll
            for (int j = 0; j < 4; j++) {
                const float fx = fmaf((float)j, t1, fx0);
                const float fy = fmaf((float)j, t4, fy0);

                const float flx = floorf(fx);
                const float fly = floorf(fy);

                const float x0 = fminf(fmaxf(flx,        0.0f), (float)(WW - 1));
                const float x1 = fminf(fmaxf(flx + 1.0f, 0.0f), (float)(WW - 1));
                const float y0 = fminf(fmaxf(fly,        0.0f), (float)(HH - 1));
                const float y1 = fminf(fmaxf(fly + 1.0f, 0.0f), (float)(HH - 1));

                const float wx0 = fmaxf(0.0f, 1.0f - fabsf(fx - x0));
                const float wx1 = fmaxf(0.0f, 1.0f - fabsf(fx - x1));
                const float wy0 = fmaxf(0.0f, 1.0f - fabsf(fy - y0));
                const float wy1 = fmaxf(0.0f, 1.0f - fabsf(fy - y1));

                float v = 0.0f;
                if ((wx0 + wx1) > 0.0f && (wy0 + wy1) > 0.0f) {
                    const int ix0 = (int)x0;
                    const int ix1 = (int)x1;
                    const int r0o = (int)y0 * WW;
                    const int r1o = (int)y1 * WW;
                    v = wy0 * (wx0 * __ldg(img + r0o + ix0) + wx1 * __ldg(img + r0o + ix1))
                      + wy1 * (wx0 * __ldg(img + r1o + ix0) + wx1 * __ldg(img + r1o + ix1));
                }
                r[j] = __saturatef(v);
            }
        }

        #pragma unroll
        for (int j = 0; j < 4; j++) out[obase + j * WW] = r[j];
    }
}

extern "C" void kernel_launch(void* const* d_in, const int* in_sizes, int n_in,
                              void* d_out, int out_size)
{
    const float* theta = (const float*)d_in[0];
    const float* image = (const float*)d_in[1];
    float* out = (float*)d_out;

    dim3 block(32, 4, 1);                 // 128 threads; tile = 32 cols x 16 rows
    dim3 grid(NBLOCKS, 1, 1);             // one resident wave, persistent loop
    affine_sample_kernel<<<grid, block>>>(theta, image, out);
}

// round 8
// speedup vs baseline: 1.2269x; 1.2269x over previous
#include <cuda_runtime.h>

// AffineTransformation: B=32, H=W=512, C=1, fp32.
// d_in[0] = theta [32,6] f32, d_in[1] = image [32,512,512,1] f32 -> out same shape.
//
// R4 structure, deepened: each thread owns 8 vertically adjacent pixels (same
// col). Interior fast path batches ALL 32 gathers before any math -> per-warp
// MLP=32 (vs 16), attacking the ~250-cycle L2-hit latency that bounds this
// kernel. Warp lanes = consecutive cols -> coalesced stores. 32-bit addressing.

#define BB 32
#define HH 512
#define WW 512
#define JP 8     // pixels per thread (vertical)

__global__ __launch_bounds__(128, 8)
void affine_sample_kernel(const float* __restrict__ theta,
                          const float* __restrict__ image,
                          float* __restrict__ out)
{
    const int b = blockIdx.z;

    const float t0 = __ldg(theta + b * 6 + 0);
    const float t1 = __ldg(theta + b * 6 + 1);
    const float t2 = __ldg(theta + b * 6 + 2);
    const float t3 = __ldg(theta + b * 6 + 3);
    const float t4 = __ldg(theta + b * 6 + 4);
    const float t5 = __ldg(theta + b * 6 + 5);

    const int col  = blockIdx.x * 32 + threadIdx.x;                  // 0..511
    const int row0 = (blockIdx.y * blockDim.y + threadIdx.y) * JP;   // 8 rows/thread

    const float inv_w = 2.0f / (float)(WW - 1);
    const float inv_h = 2.0f / (float)(HH - 1);
    const float xn  = -1.0f + (float)col  * inv_w;
    const float yn0 = -1.0f + (float)row0 * inv_h;

    // Pixel-space coords at j=0; per-row derivatives: d(fx)/d(row)=t1, d(fy)/d(row)=t4.
    const float fx0 = 0.5f * (float)(WW - 1) * (t0 * xn + t1 * yn0 + t2) + 0.5f * (float)(WW - 1);
    const float fy0 = 0.5f * (float)(HH - 1) * (t3 * xn + t4 * yn0 + t5) + 0.5f * (float)(HH - 1);
    const float fxE = fmaf((float)(JP - 1), t1, fx0);
    const float fyE = fmaf((float)(JP - 1), t4, fy0);

    const float lox = fminf(fx0, fxE), hix = fmaxf(fx0, fxE);
    const float loy = fminf(fy0, fyE), hiy = fmaxf(fy0, fyE);

    const int obase = (b * HH + row0) * WW + col;   // fits in int32

    // (c) whole span has zero coverage -> store zeros, no gathers
    if (hix <= -1.0f || lox >= (float)WW || hiy <= -1.0f || loy >= (float)HH) {
        #pragma unroll
        for (int j = 0; j < JP; j++) out[obase + j * WW] = 0.0f;
        return;
    }

    const float* __restrict__ img = image + b * (HH * WW);

    float r[JP];

    if (lox >= 0.0f && hix < (float)(WW - 1) && loy >= 0.0f && hiy < (float)(HH - 1)) {
        // (a) fully interior: no clamps, trunc == floor, plain bilinear lerp.
        // Phase 1: addresses + fractions. Phase 2: all 32 LDGs. Phase 3: math.
        float ax[JP], ay[JP];
        int   base[JP];
        #pragma unroll
        for (int j = 0; j < JP; j++) {
            const float fx = fmaf((float)j, t1, fx0);
            const float fy = fmaf((float)j, t4, fy0);
            const int ix = (int)fx;
            const int iy = (int)fy;
            ax[j] = fx - (float)ix;
            ay[j] = fy - (float)iy;
            base[j] = iy * WW + ix;
        }
        float va[JP], vb[JP], vc[JP], vd[JP];
        #pragma unroll
        for (int j = 0; j < JP; j++) {
            va[j] = __ldg(img + base[j]);
            vb[j] = __ldg(img + base[j] + 1);
            vc[j] = __ldg(img + base[j] + WW);
            vd[j] = __ldg(img + base[j] + WW + 1);
        }
        #pragma unroll
        for (int j = 0; j < JP; j++) {
            const float h0 = fmaf(ax[j], vb[j] - va[j], va[j]);
            const float h1 = fmaf(ax[j], vd[j] - vc[j], vc[j]);
            r[j] = __saturatef(fmaf(ay[j], h1 - h0, h0));
        }
    } else {
        // (b) border: full reference semantics (clip-then-delta, edge double-count)
        #pragma unroll
        for (int j = 0; j < JP; j++) {
            const float fx = fmaf((float)j, t1, fx0);
            const float fy = fmaf((float)j, t4, fy0);

            const float flx = floorf(fx);
            const float fly = floorf(fy);

            const float x0 = fminf(fmaxf(flx,        0.0f), (float)(WW - 1));
            const float x1 = fminf(fmaxf(flx + 1.0f, 0.0f), (float)(WW - 1));
            const float y0 = fminf(fmaxf(fly,        0.0f), (float)(HH - 1));
            const float y1 = fminf(fmaxf(fly + 1.0f, 0.0f), (float)(HH - 1));

            const float wx0 = fmaxf(0.0f, 1.0f - fabsf(fx - x0));
            const float wx1 = fmaxf(0.0f, 1.0f - fabsf(fx - x1));
            const float wy0 = fmaxf(0.0f, 1.0f - fabsf(fy - y0));
            const float wy1 = fmaxf(0.0f, 1.0f - fabsf(fy - y1));

            float v = 0.0f;
            if ((wx0 + wx1) > 0.0f && (wy0 + wy1) > 0.0f) {
                const int ix0 = (int)x0;
                const int ix1 = (int)x1;
                const int r0o = (int)y0 * WW;
                const int r1o = (int)y1 * WW;
                v = wy0 * (wx0 * __ldg(img + r0o + ix0) + wx1 * __ldg(img + r0o + ix1))
                  + wy1 * (wx0 * __ldg(img + r1o + ix0) + wx1 * __ldg(img + r1o + ix1));
            }
            r[j] = __saturatef(v);
        }
    }

    #pragma unroll
    for (int j = 0; j < JP; j++) out[obase + j * WW] = r[j];
}

extern "C" void kernel_launch(void* const* d_in, const int* in_sizes, int n_in,
                              void* d_out, int out_size)
{
    const float* theta = (const float*)d_in[0];
    const float* image = (const float*)d_in[1];
    float* out = (float*)d_out;

    dim3 block(32, 4, 1);                    // 128 threads; tile = 32 cols x 32 rows
    dim3 grid(WW / 32, HH / (4 * JP), BB);   // (16, 16, 32) = 8192 blocks
    affine_sample_kernel<<<grid, block>>>(theta, image, out);
}